// round 15
// baseline (speedup 1.0000x reference)
#include <cuda_runtime.h>
#include <cuda_bf16.h>
#include <cuda_fp16.h>
#include <cstdint>

// Problem constants
#define NN 10000
#define DD 128
#define NDSZ (NN * DD)

// Scratch (device globals; no allocations)
__device__ float g_qkvs[2 * NDSZ];        // Q (fp32), S (fp32)
__device__ uint4 g_kv[NN * 32];           // per node 512B: [K 128 fp16 | V 128 fp16]
__device__ float g_h[NDSZ];               // hidden after layer 0
__device__ int   g_rowptr[NN + 1];

// ===========================================================================
// row_ptr: edges sorted by src; rowptr[i] = first index with src[e] >= i
// ===========================================================================
__global__ void build_rowptr_kernel(const int* __restrict__ src, int E) {
    int i = blockIdx.x * blockDim.x + threadIdx.x;
    if (i > NN) return;
    int lo = 0, hi = E;
    while (lo < hi) {
        int mid = (lo + hi) >> 1;
        if (src[mid] < i) lo = mid + 1; else hi = mid;
    }
    g_rowptr[i] = lo;
}

// ===========================================================================
// TF32 helpers (portable mma.sync PTX — compiles under compute_103)
// ===========================================================================
__device__ __forceinline__ uint32_t f2tf32(float x) {
    uint32_t r;
    asm("cvt.rna.tf32.f32 %0, %1;" : "=r"(r) : "f"(x));
    return r;
}

__device__ __forceinline__ void mma_tf32(float* c, const uint32_t* a, const uint32_t* b) {
    asm volatile(
        "mma.sync.aligned.m16n8k8.row.col.f32.tf32.tf32.f32 "
        "{%0,%1,%2,%3}, {%4,%5,%6,%7}, {%8,%9}, {%0,%1,%2,%3};"
        : "+f"(c[0]), "+f"(c[1]), "+f"(c[2]), "+f"(c[3])
        : "r"(a[0]), "r"(a[1]), "r"(a[2]), "r"(a[3]),
          "r"(b[0]), "r"(b[1]));
}

// ===========================================================================
// Projection GEMM via TF32x3, register-prefetch pipeline, 32x64 warp tile:
// CTA tile 64x128, 4 warps (2M x 2N), 128 threads. B fragments amortized
// over 2 m-tiles -> 1.67x fewer smem wavefronts per output tile.
// grid (157, 4); 4 CTAs/SM -> 1.06 waves.
// Q,S -> fp32 g_qkvs; K,V -> fp16 g_kv [K 256B | V 256B].
// ===========================================================================
#define ASTRIDE 20
#define BSTRIDE 136

__global__ __launch_bounds__(128, 4)
void gemm_tf32_kernel(const float* __restrict__ xin,
                      const float* __restrict__ Wq, const float* __restrict__ Wk,
                      const float* __restrict__ Wv, const float* __restrict__ Ws,
                      const float* __restrict__ bq, const float* __restrict__ bk,
                      const float* __restrict__ bv, const float* __restrict__ bs,
                      int layer, int use_gh) {
    __shared__ uint32_t sAh[64 * ASTRIDE];
    __shared__ uint32_t sAl[64 * ASTRIDE];
    __shared__ uint32_t sBh[16 * BSTRIDE];
    __shared__ uint32_t sBl[16 * BSTRIDE];

    const int tid  = threadIdx.x;
    const int wid  = tid >> 5;
    const int lane = tid & 31;
    const int g    = lane >> 2;    // 0..7
    const int tg   = lane & 3;     // 0..3
    const int warpM = wid & 1;     // 0..1 (32 rows each)
    const int warpN = wid >> 1;    // 0..1 (64 cols each)

    const int rowbase = blockIdx.x * 64;
    const int mtx = blockIdx.y;

    const float* A = use_gh ? g_h : xin;
    const float* W = (mtx == 0 ? Wq : mtx == 1 ? Wk : mtx == 2 ? Wv : Ws)
                     + (size_t)layer * DD * DD;
    const float* bias = (mtx == 0 ? bq : mtx == 1 ? bk : mtx == 2 ? bv : bs)
                        + layer * DD;

    // staging indices (fixed per thread); 128 threads
    const int arow0 = tid >> 1;                 // A float4 #tid:    row 0..63
    const int ac40  = (tid & 1);                //   k-group 0..1
    const int arow1 = arow0;                    // A float4 #tid+128: same row
    const int ac41  = ac40 + 2;                 //   k-group 2..3
    const int am    = rowbase + arow0;
    const bool avalid = (am < NN);

    float acc[2][8][4];
    #pragma unroll
    for (int mi = 0; mi < 2; ++mi)
        #pragma unroll
        for (int ni = 0; ni < 8; ++ni)
            #pragma unroll
            for (int r = 0; r < 4; ++r) acc[mi][ni][r] = 0.f;

    // preload chunk 0
    float4 pA0 = make_float4(0.f, 0.f, 0.f, 0.f);
    float4 pA1 = make_float4(0.f, 0.f, 0.f, 0.f);
    if (avalid) {
        pA0 = *(const float4*)&A[(size_t)am * DD + ac40 * 4];
        pA1 = *(const float4*)&A[(size_t)am * DD + ac41 * 4];
    }
    float4 pB[4];
    #pragma unroll
    for (int r = 0; r < 4; ++r) {
        int f = tid + r * 128;
        pB[r] = *(const float4*)&W[(size_t)(f >> 5) * DD + (f & 31) * 4];
    }

    #pragma unroll
    for (int kc = 0; kc < 8; ++kc) {
        // ---- convert + STS from held registers ----
        {
            uint4 h, l;
            h.x = f2tf32(pA0.x); l.x = f2tf32(pA0.x - __uint_as_float(h.x));
            h.y = f2tf32(pA0.y); l.y = f2tf32(pA0.y - __uint_as_float(h.y));
            h.z = f2tf32(pA0.z); l.z = f2tf32(pA0.z - __uint_as_float(h.z));
            h.w = f2tf32(pA0.w); l.w = f2tf32(pA0.w - __uint_as_float(h.w));
            *(uint4*)&sAh[arow0 * ASTRIDE + ac40 * 4] = h;
            *(uint4*)&sAl[arow0 * ASTRIDE + ac40 * 4] = l;
            h.x = f2tf32(pA1.x); l.x = f2tf32(pA1.x - __uint_as_float(h.x));
            h.y = f2tf32(pA1.y); l.y = f2tf32(pA1.y - __uint_as_float(h.y));
            h.z = f2tf32(pA1.z); l.z = f2tf32(pA1.z - __uint_as_float(h.z));
            h.w = f2tf32(pA1.w); l.w = f2tf32(pA1.w - __uint_as_float(h.w));
            *(uint4*)&sAh[arow1 * ASTRIDE + ac41 * 4] = h;
            *(uint4*)&sAl[arow1 * ASTRIDE + ac41 * 4] = l;
        }
        #pragma unroll
        for (int r = 0; r < 4; ++r) {
            int f = tid + r * 128;
            int kr = f >> 5;
            int c4 = f & 31;
            uint4 h, l;
            h.x = f2tf32(pB[r].x); l.x = f2tf32(pB[r].x - __uint_as_float(h.x));
            h.y = f2tf32(pB[r].y); l.y = f2tf32(pB[r].y - __uint_as_float(h.y));
            h.z = f2tf32(pB[r].z); l.z = f2tf32(pB[r].z - __uint_as_float(h.z));
            h.w = f2tf32(pB[r].w); l.w = f2tf32(pB[r].w - __uint_as_float(h.w));
            *(uint4*)&sBh[kr * BSTRIDE + c4 * 4] = h;
            *(uint4*)&sBl[kr * BSTRIDE + c4 * 4] = l;
        }
        __syncthreads();

        // ---- prefetch next chunk (LDGs overlap with MMA below) ----
        if (kc < 7) {
            int k0 = (kc + 1) * 16;
            if (avalid) {
                pA0 = *(const float4*)&A[(size_t)am * DD + k0 + ac40 * 4];
                pA1 = *(const float4*)&A[(size_t)am * DD + k0 + ac41 * 4];
            }
            #pragma unroll
            for (int r = 0; r < 4; ++r) {
                int f = tid + r * 128;
                pB[r] = *(const float4*)&W[(size_t)(k0 + (f >> 5)) * DD + (f & 31) * 4];
            }
        }

        // ---- MMA section ----
        #pragma unroll
        for (int ks = 0; ks < 2; ++ks) {
            int ko = ks * 8;
            uint32_t ah[2][4], al[2][4];
            #pragma unroll
            for (int mi = 0; mi < 2; ++mi) {
                int r0 = (warpM * 32 + mi * 16 + g) * ASTRIDE;
                ah[mi][0] = sAh[r0 + ko + tg];
                ah[mi][1] = sAh[r0 + 8 * ASTRIDE + ko + tg];
                ah[mi][2] = sAh[r0 + ko + tg + 4];
                ah[mi][3] = sAh[r0 + 8 * ASTRIDE + ko + tg + 4];
                al[mi][0] = sAl[r0 + ko + tg];
                al[mi][1] = sAl[r0 + 8 * ASTRIDE + ko + tg];
                al[mi][2] = sAl[r0 + ko + tg + 4];
                al[mi][3] = sAl[r0 + 8 * ASTRIDE + ko + tg + 4];
            }
            #pragma unroll
            for (int ni = 0; ni < 8; ++ni) {
                int n0 = warpN * 64 + ni * 8 + g;
                uint32_t bh[2], bl[2];
                bh[0] = sBh[(ko + tg) * BSTRIDE + n0];
                bh[1] = sBh[(ko + tg + 4) * BSTRIDE + n0];
                bl[0] = sBl[(ko + tg) * BSTRIDE + n0];
                bl[1] = sBl[(ko + tg + 4) * BSTRIDE + n0];
                #pragma unroll
                for (int mi = 0; mi < 2; ++mi) {
                    mma_tf32(acc[mi][ni], ah[mi], bh);
                    mma_tf32(acc[mi][ni], al[mi], bh);
                    mma_tf32(acc[mi][ni], ah[mi], bl);
                }
            }
        }
        __syncthreads();
    }

    // ---- epilogue ----
    #pragma unroll
    for (int mi = 0; mi < 2; ++mi) {
        int m0 = rowbase + warpM * 32 + mi * 16 + g;
        int m1 = m0 + 8;
        #pragma unroll
        for (int ni = 0; ni < 8; ++ni) {
            int n = warpN * 64 + ni * 8 + tg * 2;
            float2 b2 = *(const float2*)&bias[n];
            float2 o0 = make_float2(acc[mi][ni][0] + b2.x, acc[mi][ni][1] + b2.y);
            float2 o1 = make_float2(acc[mi][ni][2] + b2.x, acc[mi][ni][3] + b2.y);
            if (mtx == 0 || mtx == 3) {
                float* outb = g_qkvs + (mtx == 0 ? 0 : NDSZ);
                if (m0 < NN) *(float2*)&outb[(size_t)m0 * DD + n] = o0;
                if (m1 < NN) *(float2*)&outb[(size_t)m1 * DD + n] = o1;
            } else {
                // node row 512B: K fp16 at [0,256), V fp16 at [256,512)
                size_t sect = (size_t)(mtx == 2 ? 256 : 0) + (size_t)n * 2;
                if (m0 < NN)
                    *(__half2*)((char*)g_kv + (size_t)m0 * 512 + sect) = __floats2half2_rn(o0.x, o0.y);
                if (m1 < NN)
                    *(__half2*)((char*)g_kv + (size_t)m1 * 512 + sect) = __floats2half2_rn(o1.x, o1.y);
            }
        }
    }
}

// ===========================================================================
// Attention (R13-proven): one warp per node; lane = (sub=lane>>3, head=lane&7).
// 4 edges/iter; per-lane full-head dot (no per-edge shuffles); softmax
// bookkeeping once per 4 edges; 4 streams flash-merged via shfl at the end.
// ===========================================================================
__global__ __launch_bounds__(256)
void attn_kernel(const float* __restrict__ xin,
                 const int* __restrict__ nbr,
                 float* __restrict__ outp, int mode) {
    int gwarp = (blockIdx.x * blockDim.x + threadIdx.x) >> 5;
    if (gwarp >= NN) return;
    const int lane = threadIdx.x & 31;
    const int sub  = lane >> 3;    // 0..3 edge slot
    const int head = lane & 7;     // 0..7
    const int i = gwarp;

    const float* Q  = g_qkvs;
    const float* Sp = g_qkvs + NDSZ;
    const float* h  = mode ? g_h : xin;

    // q head slice (16 floats), fold 1/sqrt(16)=0.25
    float q[16];
    {
        const float* qp = Q + (size_t)i * DD + head * 16;
        #pragma unroll
        for (int t = 0; t < 4; ++t) {
            float4 v = *(const float4*)(qp + 4 * t);
            q[4*t+0] = v.x * 0.25f; q[4*t+1] = v.y * 0.25f;
            q[4*t+2] = v.z * 0.25f; q[4*t+3] = v.w * 0.25f;
        }
    }

    float m = -1e30f, z = 0.f;
    float acc[16];
    #pragma unroll
    for (int t = 0; t < 16; ++t) acc[t] = 0.f;

    const int e0 = g_rowptr[i];
    const int e1 = g_rowptr[i + 1];

    for (int e = e0; e < e1; e += 4) {
        int ee = e + sub;
        bool valid = (ee < e1);
        if (!valid) ee = e1 - 1;
        int j = nbr[ee];
        const char* base = (const char*)g_kv + (size_t)j * 512 + head * 32;
        uint4 kk0 = *(const uint4*)(base);
        uint4 kk1 = *(const uint4*)(base + 16);
        uint4 vv0 = *(const uint4*)(base + 256);
        uint4 vv1 = *(const uint4*)(base + 272);

        // dot (fp32 math, fp16 inputs)
        float d = 0.f;
        {
            const __half2* kp0 = (const __half2*)&kk0;
            const __half2* kp1 = (const __half2*)&kk1;
            #pragma unroll
            for (int t = 0; t < 4; ++t) {
                float2 f = __half22float2(kp0[t]);
                d += q[2*t] * f.x + q[2*t+1] * f.y;
            }
            #pragma unroll
            for (int t = 0; t < 4; ++t) {
                float2 f = __half22float2(kp1[t]);
                d += q[8+2*t] * f.x + q[8+2*t+1] * f.y;
            }
        }

        float nm = valid ? fmaxf(m, d) : m;
        float sc = __expf(m - nm);           // 1 when nm==m
        float p  = valid ? __expf(d - nm) : 0.f;
        z = z * sc + p;
        {
            const __half2* vp0 = (const __half2*)&vv0;
            const __half2* vp1 = (const __half2*)&vv1;
            #pragma unroll
            for (int t = 0; t < 4; ++t) {
                float2 f = __half22float2(vp0[t]);
                acc[2*t]   = acc[2*t]   * sc + p * f.x;
                acc[2*t+1] = acc[2*t+1] * sc + p * f.y;
            }
            #pragma unroll
            for (int t = 0; t < 4; ++t) {
                float2 f = __half22float2(vp1[t]);
                acc[8+2*t]   = acc[8+2*t]   * sc + p * f.x;
                acc[8+2*t+1] = acc[8+2*t+1] * sc + p * f.y;
            }
        }
        m = nm;
    }

    // flash-merge the 4 sub streams (xor 8, then xor 16)
    #pragma unroll
    for (int off = 8; off <= 16; off <<= 1) {
        float om = __shfl_xor_sync(0xFFFFFFFFu, m, off);
        float oz = __shfl_xor_sync(0xFFFFFFFFu, z, off);
        float oacc[16];
        #pragma unroll
        for (int t = 0; t < 16; ++t)
            oacc[t] = __shfl_xor_sync(0xFFFFFFFFu, acc[t], off);
        float M = fmaxf(m, om);
        float c0 = __expf(m - M);
        float c1 = __expf(om - M);
        z = z * c0 + oz * c1;
        #pragma unroll
        for (int t = 0; t < 16; ++t) acc[t] = acc[t] * c0 + oacc[t] * c1;
        m = M;
    }

    if (sub == 0) {
        float inv = 1.f / z;
        const float* hp = h  + (size_t)i * DD + head * 16;
        const float* sp = Sp + (size_t)i * DD + head * 16;
        float* op = (mode == 0 ? g_h : outp) + (size_t)i * DD + head * 16;
        #pragma unroll
        for (int t = 0; t < 4; ++t) {
            float4 hv = *(const float4*)(hp + 4 * t);
            float4 sv = *(const float4*)(sp + 4 * t);
            float4 o;
            o.x = acc[4*t+0] * inv + hv.x + sv.x;
            o.y = acc[4*t+1] * inv + hv.y + sv.y;
            o.z = acc[4*t+2] * inv + hv.z + sv.z;
            o.w = acc[4*t+3] * inv + hv.w + sv.w;
            if (mode == 0) {
                o.x = fmaxf(o.x, 0.f); o.y = fmaxf(o.y, 0.f);
                o.z = fmaxf(o.z, 0.f); o.w = fmaxf(o.w, 0.f);
            }
            *(float4*)(op + 4 * t) = o;
        }
    }
}

// ===========================================================================
// Launch — only kernel launches.
// Inputs: 0=x 1=Wq 2=bq 3=Wk 4=bk 5=Wv 6=bv 7=Ws 8=bs 9=attn_window[2,E] int32
// ===========================================================================
extern "C" void kernel_launch(void* const* d_in, const int* in_sizes, int n_in,
                              void* d_out, int out_size) {
    const float* x  = (const float*)d_in[0];
    const float* Wq = (const float*)d_in[1];
    const float* bq = (const float*)d_in[2];
    const float* Wk = (const float*)d_in[3];
    const float* bk = (const float*)d_in[4];
    const float* Wv = (const float*)d_in[5];
    const float* bv = (const float*)d_in[6];
    const float* Ws = (const float*)d_in[7];
    const float* bs = (const float*)d_in[8];
    const int*   aw = (const int*)d_in[9];
    const int E = in_sizes[9] / 2;
    const int* src = aw;
    const int* dst = aw + E;

    build_rowptr_kernel<<<(NN + 256) / 256, 256>>>(src, E);

    dim3 ggrid((NN + 63) / 64, 4);
    dim3 agrid((NN * 32 + 255) / 256);

    // Layer 0
    gemm_tf32_kernel<<<ggrid, 128>>>(x, Wq, Wk, Wv, Ws, bq, bk, bv, bs, 0, 0);
    attn_kernel<<<agrid, 256>>>(x, dst, nullptr, 0);

    // Layer 1
    gemm_tf32_kernel<<<ggrid, 128>>>(x, Wq, Wk, Wv, Ws, bq, bk, bv, bs, 1, 1);
    attn_kernel<<<agrid, 256>>>(nullptr, dst, (float*)d_out, 1);
}

// round 16
// speedup vs baseline: 1.1848x; 1.1848x over previous
#include <cuda_runtime.h>
#include <cuda_bf16.h>
#include <cuda_fp16.h>
#include <cstdint>

// Problem constants
#define NN 10000
#define DD 128
#define NDSZ (NN * DD)

// Scratch (device globals; no allocations)
__device__ float g_qkvs[2 * NDSZ];        // Q (fp32), S (fp32)
__device__ uint4 g_kv[NN * 32];           // per node 512B: [K 128 fp16 | V 128 fp16]
__device__ float g_h[NDSZ];               // hidden after layer 0
__device__ int   g_rowptr[NN + 1];

// ===========================================================================
// row_ptr: edges sorted by src; rowptr[i] = first index with src[e] >= i
// ===========================================================================
__global__ void build_rowptr_kernel(const int* __restrict__ src, int E) {
    int i = blockIdx.x * blockDim.x + threadIdx.x;
    if (i > NN) return;
    int lo = 0, hi = E;
    while (lo < hi) {
        int mid = (lo + hi) >> 1;
        if (src[mid] < i) lo = mid + 1; else hi = mid;
    }
    g_rowptr[i] = lo;
}

// ===========================================================================
// TF32 helpers (portable mma.sync PTX — compiles under compute_103)
// ===========================================================================
__device__ __forceinline__ uint32_t f2tf32(float x) {
    uint32_t r;
    asm("cvt.rna.tf32.f32 %0, %1;" : "=r"(r) : "f"(x));
    return r;
}

__device__ __forceinline__ void mma_tf32(float* c, const uint32_t* a, const uint32_t* b) {
    asm volatile(
        "mma.sync.aligned.m16n8k8.row.col.f32.tf32.tf32.f32 "
        "{%0,%1,%2,%3}, {%4,%5,%6,%7}, {%8,%9}, {%0,%1,%2,%3};"
        : "+f"(c[0]), "+f"(c[1]), "+f"(c[2]), "+f"(c[3])
        : "r"(a[0]), "r"(a[1]), "r"(a[2]), "r"(a[3]),
          "r"(b[0]), "r"(b[1]));
}

// ===========================================================================
// Projection GEMM via TF32x3 with register-prefetch pipeline (R14-proven):
// CTA tile 64x128, 8 warps, warp tile 16x64, grid (157, 4).
// Q,S -> fp32 g_qkvs; K,V -> fp16 g_kv [K 256B | V 256B].
// ===========================================================================
#define ASTRIDE 20
#define BSTRIDE 136

__global__ __launch_bounds__(256, 3)
void gemm_tf32_kernel(const float* __restrict__ xin,
                      const float* __restrict__ Wq, const float* __restrict__ Wk,
                      const float* __restrict__ Wv, const float* __restrict__ Ws,
                      const float* __restrict__ bq, const float* __restrict__ bk,
                      const float* __restrict__ bv, const float* __restrict__ bs,
                      int layer, int use_gh) {
    __shared__ uint32_t sAh[64 * ASTRIDE];
    __shared__ uint32_t sAl[64 * ASTRIDE];
    __shared__ uint32_t sBh[16 * BSTRIDE];
    __shared__ uint32_t sBl[16 * BSTRIDE];

    const int tid  = threadIdx.x;
    const int wid  = tid >> 5;
    const int lane = tid & 31;
    const int g    = lane >> 2;    // 0..7
    const int tg   = lane & 3;     // 0..3
    const int warpM = wid & 3;     // 0..3 (16 rows each)
    const int warpN = wid >> 2;    // 0..1 (64 cols each)

    const int rowbase = blockIdx.x * 64;
    const int mtx = blockIdx.y;

    const float* A = use_gh ? g_h : xin;
    const float* W = (mtx == 0 ? Wq : mtx == 1 ? Wk : mtx == 2 ? Wv : Ws)
                     + (size_t)layer * DD * DD;
    const float* bias = (mtx == 0 ? bq : mtx == 1 ? bk : mtx == 2 ? bv : bs)
                        + layer * DD;

    // staging indices (fixed per thread)
    const int arow = tid >> 2;          // 0..63
    const int ac4  = tid & 3;           // k group of 4
    const int am   = rowbase + arow;
    const bool avalid = (am < NN);
    const int bkr0 = tid >> 5;          // 0..7   (r=0)
    const int bc40 = tid & 31;
    const int bkr1 = (tid + 256) >> 5;  // 8..15  (r=1)
    const int bc41 = bc40;

    float acc[8][4];
    #pragma unroll
    for (int ni = 0; ni < 8; ++ni)
        #pragma unroll
        for (int r = 0; r < 4; ++r) acc[ni][r] = 0.f;

    // preload chunk 0
    float4 pA = make_float4(0.f, 0.f, 0.f, 0.f);
    if (avalid) pA = *(const float4*)&A[(size_t)am * DD + 0 + ac4 * 4];
    float4 pB0 = *(const float4*)&W[(size_t)(0 + bkr0) * DD + bc40 * 4];
    float4 pB1 = *(const float4*)&W[(size_t)(0 + bkr1) * DD + bc41 * 4];

    #pragma unroll
    for (int kc = 0; kc < 8; ++kc) {
        // ---- convert + STS from held registers ----
        {
            uint4 h, l;
            h.x = f2tf32(pA.x); l.x = f2tf32(pA.x - __uint_as_float(h.x));
            h.y = f2tf32(pA.y); l.y = f2tf32(pA.y - __uint_as_float(h.y));
            h.z = f2tf32(pA.z); l.z = f2tf32(pA.z - __uint_as_float(h.z));
            h.w = f2tf32(pA.w); l.w = f2tf32(pA.w - __uint_as_float(h.w));
            *(uint4*)&sAh[arow * ASTRIDE + ac4 * 4] = h;
            *(uint4*)&sAl[arow * ASTRIDE + ac4 * 4] = l;
        }
        {
            uint4 h, l;
            h.x = f2tf32(pB0.x); l.x = f2tf32(pB0.x - __uint_as_float(h.x));
            h.y = f2tf32(pB0.y); l.y = f2tf32(pB0.y - __uint_as_float(h.y));
            h.z = f2tf32(pB0.z); l.z = f2tf32(pB0.z - __uint_as_float(h.z));
            h.w = f2tf32(pB0.w); l.w = f2tf32(pB0.w - __uint_as_float(h.w));
            *(uint4*)&sBh[bkr0 * BSTRIDE + bc40 * 4] = h;
            *(uint4*)&sBl[bkr0 * BSTRIDE + bc40 * 4] = l;
        }
        {
            uint4 h, l;
            h.x = f2tf32(pB1.x); l.x = f2tf32(pB1.x - __uint_as_float(h.x));
            h.y = f2tf32(pB1.y); l.y = f2tf32(pB1.y - __uint_as_float(h.y));
            h.z = f2tf32(pB1.z); l.z = f2tf32(pB1.z - __uint_as_float(h.z));
            h.w = f2tf32(pB1.w); l.w = f2tf32(pB1.w - __uint_as_float(h.w));
            *(uint4*)&sBh[bkr1 * BSTRIDE + bc41 * 4] = h;
            *(uint4*)&sBl[bkr1 * BSTRIDE + bc41 * 4] = l;
        }
        __syncthreads();

        // ---- prefetch next chunk (LDGs overlap with MMA below) ----
        if (kc < 7) {
            int k0 = (kc + 1) * 16;
            if (avalid) pA = *(const float4*)&A[(size_t)am * DD + k0 + ac4 * 4];
            pB0 = *(const float4*)&W[(size_t)(k0 + bkr0) * DD + bc40 * 4];
            pB1 = *(const float4*)&W[(size_t)(k0 + bkr1) * DD + bc41 * 4];
        }

        // ---- MMA section ----
        #pragma unroll
        for (int ks = 0; ks < 2; ++ks) {
            int ko = ks * 8;
            uint32_t ah[4], al[4];
            int r0 = (warpM * 16 + g) * ASTRIDE;
            ah[0] = sAh[r0 + ko + tg];
            ah[1] = sAh[r0 + 8 * ASTRIDE + ko + tg];
            ah[2] = sAh[r0 + ko + tg + 4];
            ah[3] = sAh[r0 + 8 * ASTRIDE + ko + tg + 4];
            al[0] = sAl[r0 + ko + tg];
            al[1] = sAl[r0 + 8 * ASTRIDE + ko + tg];
            al[2] = sAl[r0 + ko + tg + 4];
            al[3] = sAl[r0 + 8 * ASTRIDE + ko + tg + 4];
            #pragma unroll
            for (int ni = 0; ni < 8; ++ni) {
                int n0 = warpN * 64 + ni * 8 + g;
                uint32_t bh[2], bl[2];
                bh[0] = sBh[(ko + tg) * BSTRIDE + n0];
                bh[1] = sBh[(ko + tg + 4) * BSTRIDE + n0];
                bl[0] = sBl[(ko + tg) * BSTRIDE + n0];
                bl[1] = sBl[(ko + tg + 4) * BSTRIDE + n0];
                mma_tf32(acc[ni], ah, bh);
                mma_tf32(acc[ni], al, bh);
                mma_tf32(acc[ni], ah, bl);
            }
        }
        __syncthreads();
    }

    // ---- epilogue ----
    int m0 = rowbase + warpM * 16 + g;
    int m1 = m0 + 8;
    #pragma unroll
    for (int ni = 0; ni < 8; ++ni) {
        int n = warpN * 64 + ni * 8 + tg * 2;
        float2 b2 = *(const float2*)&bias[n];
        float2 o0 = make_float2(acc[ni][0] + b2.x, acc[ni][1] + b2.y);
        float2 o1 = make_float2(acc[ni][2] + b2.x, acc[ni][3] + b2.y);
        if (mtx == 0 || mtx == 3) {
            float* outb = g_qkvs + (mtx == 0 ? 0 : NDSZ);
            if (m0 < NN) *(float2*)&outb[(size_t)m0 * DD + n] = o0;
            if (m1 < NN) *(float2*)&outb[(size_t)m1 * DD + n] = o1;
        } else {
            // node row 512B: K fp16 dims at [0,256), V fp16 dims at [256,512)
            size_t sect = (size_t)(mtx == 2 ? 256 : 0) + (size_t)n * 2;
            if (m0 < NN)
                *(__half2*)((char*)g_kv + (size_t)m0 * 512 + sect) = __floats2half2_rn(o0.x, o0.y);
            if (m1 < NN)
                *(__half2*)((char*)g_kv + (size_t)m1 * 512 + sect) = __floats2half2_rn(o1.x, o1.y);
        }
    }
}

// ===========================================================================
// Attention: one warp per node; lane = (sub=lane>>3, head=lane&7).
// 4 edges/iter, per-lane full-head dot; neighbor indices software-pipelined
// one iteration ahead so the idx->KV dependency is off the critical path.
// 4 per-sub streams flash-merged via shfl at the end.
// ===========================================================================
__global__ __launch_bounds__(256)
void attn_kernel(const float* __restrict__ xin,
                 const int* __restrict__ nbr,
                 float* __restrict__ outp, int mode) {
    int gwarp = (blockIdx.x * blockDim.x + threadIdx.x) >> 5;
    if (gwarp >= NN) return;
    const int lane = threadIdx.x & 31;
    const int sub  = lane >> 3;    // 0..3 edge slot
    const int head = lane & 7;     // 0..7
    const int i = gwarp;

    const float* Q  = g_qkvs;
    const float* Sp = g_qkvs + NDSZ;
    const float* h  = mode ? g_h : xin;

    // q head slice (16 floats), fold 1/sqrt(16)=0.25
    float q[16];
    {
        const float* qp = Q + (size_t)i * DD + head * 16;
        #pragma unroll
        for (int t = 0; t < 4; ++t) {
            float4 v = *(const float4*)(qp + 4 * t);
            q[4*t+0] = v.x * 0.25f; q[4*t+1] = v.y * 0.25f;
            q[4*t+2] = v.z * 0.25f; q[4*t+3] = v.w * 0.25f;
        }
    }

    float m = -1e30f, z = 0.f;
    float acc[16];
    #pragma unroll
    for (int t = 0; t < 16; ++t) acc[t] = 0.f;

    const int e0 = g_rowptr[i];
    const int e1 = g_rowptr[i + 1];

    // prefetch first neighbor index for this sub-lane
    int ee0 = e0 + sub;
    int j = nbr[(ee0 < e1) ? ee0 : (e1 - 1)];

    for (int e = e0; e < e1; e += 4) {
        bool valid = (e + sub < e1);

        // prefetch NEXT iteration's index while this iteration's KV loads fly
        int en = e + 4 + sub;
        int jn = (en < e1) ? nbr[en] : j;

        const char* base = (const char*)g_kv + (size_t)j * 512 + head * 32;
        uint4 kk0 = *(const uint4*)(base);
        uint4 kk1 = *(const uint4*)(base + 16);
        uint4 vv0 = *(const uint4*)(base + 256);
        uint4 vv1 = *(const uint4*)(base + 272);

        // dot (fp32 math, fp16 inputs)
        float d = 0.f;
        {
            const __half2* kp0 = (const __half2*)&kk0;
            const __half2* kp1 = (const __half2*)&kk1;
            #pragma unroll
            for (int t = 0; t < 4; ++t) {
                float2 f = __half22float2(kp0[t]);
                d += q[2*t] * f.x + q[2*t+1] * f.y;
            }
            #pragma unroll
            for (int t = 0; t < 4; ++t) {
                float2 f = __half22float2(kp1[t]);
                d += q[8+2*t] * f.x + q[8+2*t+1] * f.y;
            }
        }

        float nm = valid ? fmaxf(m, d) : m;
        float sc = __expf(m - nm);           // 1 when nm==m
        float p  = valid ? __expf(d - nm) : 0.f;
        z = z * sc + p;
        {
            const __half2* vp0 = (const __half2*)&vv0;
            const __half2* vp1 = (const __half2*)&vv1;
            #pragma unroll
            for (int t = 0; t < 4; ++t) {
                float2 f = __half22float2(vp0[t]);
                acc[2*t]   = acc[2*t]   * sc + p * f.x;
                acc[2*t+1] = acc[2*t+1] * sc + p * f.y;
            }
            #pragma unroll
            for (int t = 0; t < 4; ++t) {
                float2 f = __half22float2(vp1[t]);
                acc[8+2*t]   = acc[8+2*t]   * sc + p * f.x;
                acc[8+2*t+1] = acc[8+2*t+1] * sc + p * f.y;
            }
        }
        m = nm;
        j = jn;
    }

    // flash-merge the 4 sub streams (xor 8, then xor 16)
    #pragma unroll
    for (int off = 8; off <= 16; off <<= 1) {
        float om = __shfl_xor_sync(0xFFFFFFFFu, m, off);
        float oz = __shfl_xor_sync(0xFFFFFFFFu, z, off);
        float oacc[16];
        #pragma unroll
        for (int t = 0; t < 16; ++t)
            oacc[t] = __shfl_xor_sync(0xFFFFFFFFu, acc[t], off);
        float M = fmaxf(m, om);
        float c0 = __expf(m - M);
        float c1 = __expf(om - M);
        z = z * c0 + oz * c1;
        #pragma unroll
        for (int t = 0; t < 16; ++t) acc[t] = acc[t] * c0 + oacc[t] * c1;
        m = M;
    }

    if (sub == 0) {
        float inv = 1.f / z;
        const float* hp = h  + (size_t)i * DD + head * 16;
        const float* sp = Sp + (size_t)i * DD + head * 16;
        float* op = (mode == 0 ? g_h : outp) + (size_t)i * DD + head * 16;
        #pragma unroll
        for (int t = 0; t < 4; ++t) {
            float4 hv = *(const float4*)(hp + 4 * t);
            float4 sv = *(const float4*)(sp + 4 * t);
            float4 o;
            o.x = acc[4*t+0] * inv + hv.x + sv.x;
            o.y = acc[4*t+1] * inv + hv.y + sv.y;
            o.z = acc[4*t+2] * inv + hv.z + sv.z;
            o.w = acc[4*t+3] * inv + hv.w + sv.w;
            if (mode == 0) {
                o.x = fmaxf(o.x, 0.f); o.y = fmaxf(o.y, 0.f);
                o.z = fmaxf(o.z, 0.f); o.w = fmaxf(o.w, 0.f);
            }
            *(float4*)(op + 4 * t) = o;
        }
    }
}

// ===========================================================================
// Launch — only kernel launches.
// Inputs: 0=x 1=Wq 2=bq 3=Wk 4=bk 5=Wv 6=bv 7=Ws 8=bs 9=attn_window[2,E] int32
// ===========================================================================
extern "C" void kernel_launch(void* const* d_in, const int* in_sizes, int n_in,
                              void* d_out, int out_size) {
    const float* x  = (const float*)d_in[0];
    const float* Wq = (const float*)d_in[1];
    const float* bq = (const float*)d_in[2];
    const float* Wk = (const float*)d_in[3];
    const float* bk = (const float*)d_in[4];
    const float* Wv = (const float*)d_in[5];
    const float* bv = (const float*)d_in[6];
    const float* Ws = (const float*)d_in[7];
    const float* bs = (const float*)d_in[8];
    const int*   aw = (const int*)d_in[9];
    const int E = in_sizes[9] / 2;
    const int* src = aw;
    const int* dst = aw + E;

    build_rowptr_kernel<<<(NN + 256) / 256, 256>>>(src, E);

    dim3 ggrid((NN + 63) / 64, 4);
    dim3 agrid((NN * 32 + 255) / 256);

    // Layer 0
    gemm_tf32_kernel<<<ggrid, 256>>>(x, Wq, Wk, Wv, Ws, bq, bk, bv, bs, 0, 0);
    attn_kernel<<<agrid, 256>>>(x, dst, nullptr, 0);

    // Layer 1
    gemm_tf32_kernel<<<ggrid, 256>>>(x, Wq, Wk, Wv, Ws, bq, bk, bv, bs, 1, 1);
    attn_kernel<<<agrid, 256>>>(nullptr, dst, (float*)d_out, 1);
}